// round 10
// baseline (speedup 1.0000x reference)
#include <cuda_runtime.h>
#include <cuda_fp16.h>
#include <cstdint>

#define KT       2048
#define NH       96
#define M_TILE   128
#define KB       64
#define NITER    (KT / KB)     // 32
#define NTHREADS 256

// Preconverted W halves (scratch via __device__ globals — no allocation)
__device__ __half g_Whi[NH * KT];
__device__ __half g_Wlo[NH * KT];

// ---------------- SMEM layout (bytes) ----------------
#define SM_AHI   0u              // 2 x 16384  (128 rows x 128B, x-hi halves)
#define SM_BHI   32768u          // 2 x 12288  (96 rows x 128B)
#define SM_BLO   57344u          // 2 x 12288
#define SM_TOTAL 81920u

// ---------------- helpers ----------------
__device__ __forceinline__ uint32_t smem_u32(const void* p) {
    uint32_t a;
    asm("{ .reg .u64 t; cvta.to.shared.u64 t, %1; cvt.u32.u64 %0, t; }" : "=r"(a) : "l"(p));
    return a;
}
__device__ __forceinline__ uint32_t sw128(uint32_t o) { return o ^ ((o >> 3) & 0x70u); }

__device__ __forceinline__ void sts128(uint32_t a, uint32_t v0, uint32_t v1,
                                       uint32_t v2, uint32_t v3) {
    asm volatile("st.shared.v4.b32 [%0], {%1,%2,%3,%4};"
                 :: "r"(a), "r"(v0), "r"(v1), "r"(v2), "r"(v3) : "memory");
}
__device__ __forceinline__ void cp16(uint32_t dst, const void* src) {
    asm volatile("cp.async.cg.shared.global [%0], [%1], 16;"
                 :: "r"(dst), "l"(src) : "memory");
}
__device__ __forceinline__ void cp_commit() {
    asm volatile("cp.async.commit_group;" ::: "memory");
}
__device__ __forceinline__ void cp_wait0() {
    asm volatile("cp.async.wait_group 0;" ::: "memory");
}
__device__ __forceinline__ void ldsm_x4(uint32_t* r, uint32_t addr) {
    asm volatile("ldmatrix.sync.aligned.m8n8.x4.shared.b16 {%0,%1,%2,%3}, [%4];"
                 : "=r"(r[0]), "=r"(r[1]), "=r"(r[2]), "=r"(r[3]) : "r"(addr));
}
__device__ __forceinline__ void mma16816(float* c, const uint32_t* a,
                                         uint32_t b0, uint32_t b1) {
    asm volatile(
        "mma.sync.aligned.m16n8k16.row.col.f32.f16.f16.f32 "
        "{%0,%1,%2,%3}, {%4,%5,%6,%7}, {%8,%9}, {%0,%1,%2,%3};"
        : "+f"(c[0]), "+f"(c[1]), "+f"(c[2]), "+f"(c[3])
        : "r"(a[0]), "r"(a[1]), "r"(a[2]), "r"(a[3]), "r"(b0), "r"(b1));
}

// ---------------- W pre-convert kernel ----------------
__global__ void __launch_bounds__(256) convW_kernel(const float* __restrict__ W) {
    int i = blockIdx.x * 256 + threadIdx.x;
    float w = W[i];
    __half h = __float2half(w);
    g_Whi[i] = h;
    g_Wlo[i] = __float2half(w - __half2float(h));
}

// ---------------- main GEMM kernel ----------------
__global__ void __launch_bounds__(NTHREADS, 1)
mh96_kernel(const float* __restrict__ x, const float* __restrict__ bias,
            float* __restrict__ out)
{
    extern __shared__ __align__(1024) char smem[];
    const uint32_t sb = smem_u32(smem);
    const int tid = threadIdx.x;
    const int wid = tid >> 5;
    const int lid = tid & 31;
    const int m0  = blockIdx.x * M_TILE;

    const int wm = wid & 1;      // m-half: rows wm*64
    const int wn = wid >> 1;     // n-quarter: cols wn*24

    // x staging: converted to half2 at LDG time (16 regs)
    uint32_t xh[4][4];

    auto loadX = [&](int kc) {
#pragma unroll
        for (int j = 0; j < 4; ++j) {
            int s = j * NTHREADS + tid;          // 1024 slots = 128 rows x 8 (16B units)
            int row = s >> 3, c8 = s & 7;
            const float4* p = reinterpret_cast<const float4*>(
                x + (size_t)(m0 + row) * KT + kc * KB + c8 * 8);
            float4 v0 = p[0], v1 = p[1];
            __half2 h0 = __float22half2_rn(make_float2(v0.x, v0.y));
            __half2 h1 = __float22half2_rn(make_float2(v0.z, v0.w));
            __half2 h2 = __float22half2_rn(make_float2(v1.x, v1.y));
            __half2 h3 = __float22half2_rn(make_float2(v1.z, v1.w));
            xh[j][0] = *reinterpret_cast<uint32_t*>(&h0);
            xh[j][1] = *reinterpret_cast<uint32_t*>(&h1);
            xh[j][2] = *reinterpret_cast<uint32_t*>(&h2);
            xh[j][3] = *reinterpret_cast<uint32_t*>(&h3);
        }
    };
    auto cpW = [&](int kc, int buf) {
#pragma unroll
        for (int j = 0; j < 3; ++j) {
            int s = j * NTHREADS + tid;          // 768 slots = 96 rows x 8
            int row = s >> 3, c8 = s & 7;
            uint32_t off = sw128((uint32_t)(row * 128 + c8 * 16));
            size_t go = (size_t)row * KT + kc * KB + c8 * 8;
            cp16(sb + SM_BHI + (uint32_t)buf * 12288u + off, g_Whi + go);
            cp16(sb + SM_BLO + (uint32_t)buf * 12288u + off, g_Wlo + go);
        }
    };
    auto stsX = [&](int buf) {
#pragma unroll
        for (int j = 0; j < 4; ++j) {
            int s = j * NTHREADS + tid;
            int row = s >> 3, c8 = s & 7;
            uint32_t off = sw128((uint32_t)(row * 128 + c8 * 16));
            sts128(sb + SM_AHI + (uint32_t)buf * 16384u + off,
                   xh[j][0], xh[j][1], xh[j][2], xh[j][3]);
        }
    };

    float acc[4][3][4];
#pragma unroll
    for (int mt = 0; mt < 4; ++mt)
#pragma unroll
        for (int nt = 0; nt < 3; ++nt)
#pragma unroll
            for (int i = 0; i < 4; ++i) acc[mt][nt][i] = 0.f;

    // ldmatrix per-thread address components
    const int a_row8 = wm * 64 + (lid & 7) + ((lid >> 3) & 1) * 8;   // + mt*16
    const int a_koff = ((lid >> 4) & 1) * 16;                        // + ks*32
    const int b_row  = wn * 24 + (lid & 7);                          // + nt*8
    const int b_koff = (lid >> 3) * 16;                              // + kp*64

    // ---------------- prologue: fill buffer 0 ----------------
    loadX(0);
    cpW(0, 0);
    cp_commit();
    stsX(0);
    cp_wait0();
    __syncthreads();

    // fragment double buffers (all indices compile-time)
    uint32_t a0[4][4], a1[4][4];
    uint32_t b0h[3][4], b0l[3][4], b1h[3][4], b1l[3][4];

// one ldsm of an A fragment (compile-time ks, mt)
#define LDA1(DST, KS, MT) \
    ldsm_x4(DST[MT], ah_b + sw128((uint32_t)((a_row8 + (MT) * 16) * 128 + (KS) * 32 + a_koff)));
// one ldsm of a B-hi / B-lo fragment (compile-time kp, nt)
#define LDBH1(DST, KP, NT) \
    ldsm_x4(DST[NT], bh_b + sw128((uint32_t)((b_row + (NT) * 8) * 128 + (KP) * 64 + b_koff)));
#define LDBL1(DST, KP, NT) \
    ldsm_x4(DST[NT], bl_b + sw128((uint32_t)((b_row + (NT) * 8) * 128 + (KP) * 64 + b_koff)));
// 3 mmas (one mt row across nt=0..2), compile-time B reg indices
#define MMA3(A, B, I0, I1, MT) \
    mma16816(acc[MT][0], A[MT], B[0][I0], B[0][I1]); \
    mma16816(acc[MT][1], A[MT], B[1][I0], B[1][I1]); \
    mma16816(acc[MT][2], A[MT], B[2][I0], B[2][I1]);

    for (int it = 0; it < NITER; ++it) {
        const int buf  = it & 1;
        const int nbuf = buf ^ 1;

        // next chunk's global loads, issued first (hide under MMA)
        if (it + 1 < NITER) {
            loadX(it + 1);
            cpW(it + 1, nbuf);
            cp_commit();
        }

        const uint32_t ah_b = sb + SM_AHI + (uint32_t)buf * 16384u;
        const uint32_t bh_b = sb + SM_BHI + (uint32_t)buf * 12288u;
        const uint32_t bl_b = sb + SM_BLO + (uint32_t)buf * 12288u;

        // head: first fragment set (only serial section of the iter)
        LDBH1(b0h, 0, 0) LDBH1(b0h, 0, 1) LDBH1(b0h, 0, 2)
        LDBL1(b0l, 0, 0) LDBL1(b0l, 0, 1) LDBL1(b0l, 0, 2)
        LDA1(a0, 0, 0) LDA1(a0, 0, 1) LDA1(a0, 0, 2) LDA1(a0, 0, 3)

        // S0: ks=0 (kp0, B regs 0,1); interleave prefetch a1 <- ks=1
        MMA3(a0, b0h, 0, 1, 0) LDA1(a1, 1, 0)
        MMA3(a0, b0h, 0, 1, 1) LDA1(a1, 1, 1)
        MMA3(a0, b0h, 0, 1, 2) LDA1(a1, 1, 2)
        MMA3(a0, b0h, 0, 1, 3) LDA1(a1, 1, 3)
        MMA3(a0, b0l, 0, 1, 0)
        MMA3(a0, b0l, 0, 1, 1)
        MMA3(a0, b0l, 0, 1, 2)
        MMA3(a0, b0l, 0, 1, 3)

        // S1: ks=1 (kp0, B regs 2,3); prefetch b1 (kp=1) + a0 <- ks=2
        MMA3(a1, b0h, 2, 3, 0) LDBH1(b1h, 1, 0) LDBH1(b1h, 1, 1)
        MMA3(a1, b0h, 2, 3, 1) LDBH1(b1h, 1, 2)
        MMA3(a1, b0h, 2, 3, 2) LDBL1(b1l, 1, 0)
        MMA3(a1, b0h, 2, 3, 3) LDBL1(b1l, 1, 1) LDBL1(b1l, 1, 2)
        MMA3(a1, b0l, 2, 3, 0) LDA1(a0, 2, 0)
        MMA3(a1, b0l, 2, 3, 1) LDA1(a0, 2, 1)
        MMA3(a1, b0l, 2, 3, 2) LDA1(a0, 2, 2)
        MMA3(a1, b0l, 2, 3, 3) LDA1(a0, 2, 3)

        // S2: ks=2 (kp1, B regs 0,1); prefetch a1 <- ks=3
        MMA3(a0, b1h, 0, 1, 0) LDA1(a1, 3, 0)
        MMA3(a0, b1h, 0, 1, 1) LDA1(a1, 3, 1)
        MMA3(a0, b1h, 0, 1, 2) LDA1(a1, 3, 2)
        MMA3(a0, b1h, 0, 1, 3) LDA1(a1, 3, 3)
        MMA3(a0, b1l, 0, 1, 0)
        MMA3(a0, b1l, 0, 1, 1)
        MMA3(a0, b1l, 0, 1, 2)
        MMA3(a0, b1l, 0, 1, 3)

        // S3: ks=3 (kp1, B regs 2,3); pure mma tail
        MMA3(a1, b1h, 2, 3, 0)
        MMA3(a1, b1h, 2, 3, 1)
        MMA3(a1, b1h, 2, 3, 2)
        MMA3(a1, b1h, 2, 3, 3)
        MMA3(a1, b1l, 2, 3, 0)
        MMA3(a1, b1l, 2, 3, 1)
        MMA3(a1, b1l, 2, 3, 2)
        MMA3(a1, b1l, 2, 3, 3)

        if (it + 1 < NITER) {
            stsX(nbuf);
            cp_wait0();
        }
        __syncthreads();
    }

#undef LDA1
#undef LDBH1
#undef LDBL1
#undef MMA3

    // ---------------- epilogue ----------------
    const int r0 = m0 + wm * 64 + (lid >> 2);
    const int c0 = wn * 24 + (lid & 3) * 2;
#pragma unroll
    for (int nt = 0; nt < 3; ++nt) {
        const int col = c0 + nt * 8;
        const float b0 = bias[col], b1 = bias[col + 1];
#pragma unroll
        for (int mt = 0; mt < 4; ++mt) {
            const int row = r0 + mt * 16;
            float2 v0 = make_float2(acc[mt][nt][0] + b0, acc[mt][nt][1] + b1);
            float2 v1 = make_float2(acc[mt][nt][2] + b0, acc[mt][nt][3] + b1);
            *reinterpret_cast<float2*>(out + (size_t)row * NH + col) = v0;
            *reinterpret_cast<float2*>(out + (size_t)(row + 8) * NH + col) = v1;
        }
    }
}

extern "C" void kernel_launch(void* const* d_in, const int* in_sizes, int n_in,
                              void* d_out, int out_size) {
    const float* x    = (const float*)d_in[0];  // [16384, 2048]
    const float* W    = (const float*)d_in[1];  // [96, 2048]
    const float* bias = (const float*)d_in[2];  // [96]
    float* out        = (float*)d_out;          // [16384, 96]

    cudaFuncSetAttribute(mh96_kernel, cudaFuncAttributeMaxDynamicSharedMemorySize, SM_TOTAL);
    convW_kernel<<<(NH * KT) / 256, 256>>>(W);
    mh96_kernel<<<16384 / M_TILE, NTHREADS, SM_TOTAL>>>(x, bias, out);
}

// round 11
// speedup vs baseline: 1.2183x; 1.2183x over previous
#include <cuda_runtime.h>
#include <cuda_fp16.h>
#include <cstdint>

#define KT       2048
#define NH       96
#define M_TILE   128
#define KB       64
#define NITER    (KT / KB)     // 32
#define NTHREADS 256

// Preconverted W (fp16) — scratch via __device__ global, no allocation
__device__ __half g_Whi[NH * KT];

// ---------------- SMEM layout (bytes) ----------------
#define SM_AHI   0u              // 2 x 16384  (128 rows x 128B, x fp16)
#define SM_BHI   32768u          // 2 x 12288  (96 rows x 128B, W fp16)
#define SM_TOTAL 57344u

// ---------------- helpers ----------------
__device__ __forceinline__ uint32_t smem_u32(const void* p) {
    uint32_t a;
    asm("{ .reg .u64 t; cvta.to.shared.u64 t, %1; cvt.u32.u64 %0, t; }" : "=r"(a) : "l"(p));
    return a;
}
__device__ __forceinline__ uint32_t sw128(uint32_t o) { return o ^ ((o >> 3) & 0x70u); }

__device__ __forceinline__ void sts128(uint32_t a, uint32_t v0, uint32_t v1,
                                       uint32_t v2, uint32_t v3) {
    asm volatile("st.shared.v4.b32 [%0], {%1,%2,%3,%4};"
                 :: "r"(a), "r"(v0), "r"(v1), "r"(v2), "r"(v3) : "memory");
}
__device__ __forceinline__ void cp16(uint32_t dst, const void* src) {
    asm volatile("cp.async.cg.shared.global [%0], [%1], 16;"
                 :: "r"(dst), "l"(src) : "memory");
}
__device__ __forceinline__ void cp_commit() {
    asm volatile("cp.async.commit_group;" ::: "memory");
}
__device__ __forceinline__ void cp_wait0() {
    asm volatile("cp.async.wait_group 0;" ::: "memory");
}
__device__ __forceinline__ void ldsm_x4(uint32_t* r, uint32_t addr) {
    asm volatile("ldmatrix.sync.aligned.m8n8.x4.shared.b16 {%0,%1,%2,%3}, [%4];"
                 : "=r"(r[0]), "=r"(r[1]), "=r"(r[2]), "=r"(r[3]) : "r"(addr));
}
__device__ __forceinline__ void mma16816(float* c, const uint32_t* a,
                                         uint32_t b0, uint32_t b1) {
    asm volatile(
        "mma.sync.aligned.m16n8k16.row.col.f32.f16.f16.f32 "
        "{%0,%1,%2,%3}, {%4,%5,%6,%7}, {%8,%9}, {%0,%1,%2,%3};"
        : "+f"(c[0]), "+f"(c[1]), "+f"(c[2]), "+f"(c[3])
        : "r"(a[0]), "r"(a[1]), "r"(a[2]), "r"(a[3]), "r"(b0), "r"(b1));
}

// ---------------- W pre-convert kernel ----------------
__global__ void __launch_bounds__(256) convW_kernel(const float* __restrict__ W) {
    int i = blockIdx.x * 256 + threadIdx.x;
    g_Whi[i] = __float2half(W[i]);
}

// ---------------- main GEMM kernel ----------------
__global__ void __launch_bounds__(NTHREADS, 1)
mh96_kernel(const float* __restrict__ x, const float* __restrict__ bias,
            float* __restrict__ out)
{
    extern __shared__ __align__(1024) char smem[];
    const uint32_t sb = smem_u32(smem);
    const int tid = threadIdx.x;
    const int wid = tid >> 5;
    const int lid = tid & 31;
    const int m0  = blockIdx.x * M_TILE;

    const int wm = wid & 1;      // m-half: rows wm*64
    const int wn = wid >> 1;     // n-quarter: cols wn*24

    // x staging: converted to half2 at LDG time (16 regs)
    uint32_t xh[4][4];

    auto loadX = [&](int kc) {
#pragma unroll
        for (int j = 0; j < 4; ++j) {
            int s = j * NTHREADS + tid;          // 1024 slots = 128 rows x 8 (16B units)
            int row = s >> 3, c8 = s & 7;
            const float4* p = reinterpret_cast<const float4*>(
                x + (size_t)(m0 + row) * KT + kc * KB + c8 * 8);
            float4 v0 = p[0], v1 = p[1];
            __half2 h0 = __float22half2_rn(make_float2(v0.x, v0.y));
            __half2 h1 = __float22half2_rn(make_float2(v0.z, v0.w));
            __half2 h2 = __float22half2_rn(make_float2(v1.x, v1.y));
            __half2 h3 = __float22half2_rn(make_float2(v1.z, v1.w));
            xh[j][0] = *reinterpret_cast<uint32_t*>(&h0);
            xh[j][1] = *reinterpret_cast<uint32_t*>(&h1);
            xh[j][2] = *reinterpret_cast<uint32_t*>(&h2);
            xh[j][3] = *reinterpret_cast<uint32_t*>(&h3);
        }
    };
    auto cpW = [&](int kc, int buf) {
#pragma unroll
        for (int j = 0; j < 3; ++j) {
            int s = j * NTHREADS + tid;          // 768 slots = 96 rows x 8
            int row = s >> 3, c8 = s & 7;
            uint32_t off = sw128((uint32_t)(row * 128 + c8 * 16));
            size_t go = (size_t)row * KT + kc * KB + c8 * 8;
            cp16(sb + SM_BHI + (uint32_t)buf * 12288u + off, g_Whi + go);
        }
    };
    auto stsX = [&](int buf) {
#pragma unroll
        for (int j = 0; j < 4; ++j) {
            int s = j * NTHREADS + tid;
            int row = s >> 3, c8 = s & 7;
            uint32_t off = sw128((uint32_t)(row * 128 + c8 * 16));
            sts128(sb + SM_AHI + (uint32_t)buf * 16384u + off,
                   xh[j][0], xh[j][1], xh[j][2], xh[j][3]);
        }
    };

    float acc[4][3][4];
#pragma unroll
    for (int mt = 0; mt < 4; ++mt)
#pragma unroll
        for (int nt = 0; nt < 3; ++nt)
#pragma unroll
            for (int i = 0; i < 4; ++i) acc[mt][nt][i] = 0.f;

    // ldmatrix per-thread address components
    const int a_row8 = wm * 64 + (lid & 7) + ((lid >> 3) & 1) * 8;   // + mt*16
    const int a_koff = ((lid >> 4) & 1) * 16;                        // + ks*32
    const int b_row  = wn * 24 + (lid & 7);                          // + nt*8
    const int b_koff = (lid >> 3) * 16;                              // + kp*64

    // ---------------- prologue: fill buffer 0 ----------------
    loadX(0);
    cpW(0, 0);
    cp_commit();
    stsX(0);
    cp_wait0();
    __syncthreads();

    for (int it = 0; it < NITER; ++it) {
        const int buf  = it & 1;
        const int nbuf = buf ^ 1;

        // next chunk's global loads, hidden under this iter's MMA
        if (it + 1 < NITER) {
            loadX(it + 1);
            cpW(it + 1, nbuf);
            cp_commit();
        }

        const uint32_t ah_b = sb + SM_AHI + (uint32_t)buf * 16384u;
        const uint32_t bh_b = sb + SM_BHI + (uint32_t)buf * 12288u;

#pragma unroll
        for (int kp = 0; kp < 2; ++kp) {
            uint32_t bh[3][4];
#pragma unroll
            for (int nt = 0; nt < 3; ++nt) {
                uint32_t boff = sw128((uint32_t)((b_row + nt * 8) * 128 + kp * 64 + b_koff));
                ldsm_x4(bh[nt], bh_b + boff);
            }
#pragma unroll
            for (int ks2 = 0; ks2 < 2; ++ks2) {
                const int ks = kp * 2 + ks2;
                uint32_t a[4][4];
#pragma unroll
                for (int mt = 0; mt < 4; ++mt) {
                    uint32_t aoff = sw128((uint32_t)((a_row8 + mt * 16) * 128 + ks * 32 + a_koff));
                    ldsm_x4(a[mt], ah_b + aoff);
                }
#pragma unroll
                for (int mt = 0; mt < 4; ++mt)
#pragma unroll
                    for (int nt = 0; nt < 3; ++nt)
                        mma16816(acc[mt][nt], a[mt], bh[nt][2 * ks2], bh[nt][2 * ks2 + 1]);
            }
        }

        if (it + 1 < NITER) {
            stsX(nbuf);
            cp_wait0();
        }
        __syncthreads();
    }

    // ---------------- epilogue ----------------
    const int r0 = m0 + wm * 64 + (lid >> 2);
    const int c0 = wn * 24 + (lid & 3) * 2;
#pragma unroll
    for (int nt = 0; nt < 3; ++nt) {
        const int col = c0 + nt * 8;
        const float b0 = bias[col], b1 = bias[col + 1];
#pragma unroll
        for (int mt = 0; mt < 4; ++mt) {
            const int row = r0 + mt * 16;
            float2 v0 = make_float2(acc[mt][nt][0] + b0, acc[mt][nt][1] + b1);
            float2 v1 = make_float2(acc[mt][nt][2] + b0, acc[mt][nt][3] + b1);
            *reinterpret_cast<float2*>(out + (size_t)row * NH + col) = v0;
            *reinterpret_cast<float2*>(out + (size_t)(row + 8) * NH + col) = v1;
        }
    }
}

extern "C" void kernel_launch(void* const* d_in, const int* in_sizes, int n_in,
                              void* d_out, int out_size) {
    const float* x    = (const float*)d_in[0];  // [16384, 2048]
    const float* W    = (const float*)d_in[1];  // [96, 2048]
    const float* bias = (const float*)d_in[2];  // [96]
    float* out        = (float*)d_out;          // [16384, 96]

    cudaFuncSetAttribute(mh96_kernel, cudaFuncAttributeMaxDynamicSharedMemorySize, SM_TOTAL);
    convW_kernel<<<(NH * KT) / 256, 256>>>(W);
    mh96_kernel<<<16384 / M_TILE, NTHREADS, SM_TOTAL>>>(x, bias, out);
}

// round 12
// speedup vs baseline: 1.7400x; 1.4282x over previous
#include <cuda_runtime.h>
#include <cuda_fp16.h>
#include <cstdint>

#define KT       2048
#define NH       96
#define M_TILE   128
#define KB       64
#define NITER    (KT / KB)     // 32
#define NTHREADS 256
#define NSTAGE   3

// Preconverted W (fp16) — scratch via __device__ global, no allocation
__device__ __half g_Whi[NH * KT];

// ---------------- SMEM layout (bytes) ----------------
#define SM_A     0u              // 3 x 16384  (128 rows x 128B, x fp16)
#define SM_B     49152u          // 3 x 12288  (96 rows x 128B, W fp16)
#define SM_TOTAL 86016u

// ---------------- helpers ----------------
__device__ __forceinline__ uint32_t smem_u32(const void* p) {
    uint32_t a;
    asm("{ .reg .u64 t; cvta.to.shared.u64 t, %1; cvt.u32.u64 %0, t; }" : "=r"(a) : "l"(p));
    return a;
}
__device__ __forceinline__ uint32_t sw128(uint32_t o) { return o ^ ((o >> 3) & 0x70u); }

__device__ __forceinline__ void sts128(uint32_t a, uint32_t v0, uint32_t v1,
                                       uint32_t v2, uint32_t v3) {
    asm volatile("st.shared.v4.b32 [%0], {%1,%2,%3,%4};"
                 :: "r"(a), "r"(v0), "r"(v1), "r"(v2), "r"(v3) : "memory");
}
__device__ __forceinline__ void cp16(uint32_t dst, const void* src) {
    asm volatile("cp.async.cg.shared.global [%0], [%1], 16;"
                 :: "r"(dst), "l"(src) : "memory");
}
__device__ __forceinline__ void cp_commit() {
    asm volatile("cp.async.commit_group;" ::: "memory");
}
__device__ __forceinline__ void cp_wait0() {
    asm volatile("cp.async.wait_group 0;" ::: "memory");
}
__device__ __forceinline__ void cp_wait1() {
    asm volatile("cp.async.wait_group 1;" ::: "memory");
}
__device__ __forceinline__ void ldsm_x4(uint32_t* r, uint32_t addr) {
    asm volatile("ldmatrix.sync.aligned.m8n8.x4.shared.b16 {%0,%1,%2,%3}, [%4];"
                 : "=r"(r[0]), "=r"(r[1]), "=r"(r[2]), "=r"(r[3]) : "r"(addr));
}
__device__ __forceinline__ void mma16816(float* c, const uint32_t* a,
                                         uint32_t b0, uint32_t b1) {
    asm volatile(
        "mma.sync.aligned.m16n8k16.row.col.f32.f16.f16.f32 "
        "{%0,%1,%2,%3}, {%4,%5,%6,%7}, {%8,%9}, {%0,%1,%2,%3};"
        : "+f"(c[0]), "+f"(c[1]), "+f"(c[2]), "+f"(c[3])
        : "r"(a[0]), "r"(a[1]), "r"(a[2]), "r"(a[3]), "r"(b0), "r"(b1));
}

// ---------------- W pre-convert kernel ----------------
__global__ void __launch_bounds__(256) convW_kernel(const float* __restrict__ W) {
    int i = blockIdx.x * 256 + threadIdx.x;
    g_Whi[i] = __float2half(W[i]);
}

// ---------------- main GEMM kernel ----------------
__global__ void __launch_bounds__(NTHREADS, 1)
mh96_kernel(const float* __restrict__ x, const float* __restrict__ bias,
            float* __restrict__ out)
{
    extern __shared__ __align__(1024) char smem[];
    const uint32_t sb = smem_u32(smem);
    const int tid = threadIdx.x;
    const int wid = tid >> 5;
    const int lid = tid & 31;
    const int m0  = blockIdx.x * M_TILE;

    const int wm = wid & 1;      // m-half: rows wm*64
    const int wn = wid >> 1;     // n-quarter: cols wn*24

    // raw f32 staging for x (distance-2 prefetch; converted one iter later)
    float4 xr[4][2];

    auto loadXf = [&](int kc) {      // issue LDGs only; no dependent math
#pragma unroll
        for (int j = 0; j < 4; ++j) {
            int s = j * NTHREADS + tid;          // 1024 slots = 128 rows x 8 (16B units)
            int row = s >> 3, c8 = s & 7;
            const float4* p = reinterpret_cast<const float4*>(
                x + (size_t)(m0 + row) * KT + kc * KB + c8 * 8);
            xr[j][0] = p[0];
            xr[j][1] = p[1];
        }
    };
    auto cpW = [&](int kc, int buf) {
#pragma unroll
        for (int j = 0; j < 3; ++j) {
            int s = j * NTHREADS + tid;          // 768 slots = 96 rows x 8
            int row = s >> 3, c8 = s & 7;
            uint32_t off = sw128((uint32_t)(row * 128 + c8 * 16));
            size_t go = (size_t)row * KT + kc * KB + c8 * 8;
            cp16(sb + SM_B + (uint32_t)buf * 12288u + off, g_Whi + go);
        }
    };
    auto cvtStsX = [&](int buf) {    // convert staged f32 -> half2, store to ring buf
#pragma unroll
        for (int j = 0; j < 4; ++j) {
            int s = j * NTHREADS + tid;
            int row = s >> 3, c8 = s & 7;
            uint32_t off = sw128((uint32_t)(row * 128 + c8 * 16));
            __half2 h0 = __float22half2_rn(make_float2(xr[j][0].x, xr[j][0].y));
            __half2 h1 = __float22half2_rn(make_float2(xr[j][0].z, xr[j][0].w));
            __half2 h2 = __float22half2_rn(make_float2(xr[j][1].x, xr[j][1].y));
            __half2 h3 = __float22half2_rn(make_float2(xr[j][1].z, xr[j][1].w));
            sts128(sb + SM_A + (uint32_t)buf * 16384u + off,
                   *reinterpret_cast<uint32_t*>(&h0), *reinterpret_cast<uint32_t*>(&h1),
                   *reinterpret_cast<uint32_t*>(&h2), *reinterpret_cast<uint32_t*>(&h3));
        }
    };

    float acc[4][3][4];
#pragma unroll
    for (int mt = 0; mt < 4; ++mt)
#pragma unroll
        for (int nt = 0; nt < 3; ++nt)
#pragma unroll
            for (int i = 0; i < 4; ++i) acc[mt][nt][i] = 0.f;

    // ldmatrix per-thread address components
    const int a_row8 = wm * 64 + (lid & 7) + ((lid >> 3) & 1) * 8;   // + mt*16
    const int a_koff = ((lid >> 4) & 1) * 16;                        // + ks*32
    const int b_row  = wn * 24 + (lid & 7);                          // + nt*8
    const int b_koff = (lid >> 3) * 16;                              // + kp*64

    // ---------------- prologue: fill stage 0, prefetch stage 1 ----------------
    loadXf(0);
    cpW(0, 0);  cp_commit();
    cvtStsX(0);                      // stalls on LDG(0) — prologue only
    loadXf(1);                       // xr <- chunk 1 (in flight)
    cpW(1, 1);  cp_commit();
    cp_wait1();                      // cpW(0) complete
    __syncthreads();                 // stage 0 ready

    for (int it = 0; it < NITER; ++it) {
        const int buf = it % NSTAGE;

        // stage it+1: convert + store x (LDG completed during previous iter's MMA)
        if (it + 1 < NITER) cvtStsX((it + 1) % NSTAGE);
        // stage it+2: issue global loads (a full iteration of slack)
        if (it + 2 < NITER) {
            loadXf(it + 2);
            cpW(it + 2, (it + 2) % NSTAGE);
            cp_commit();
        }

        const uint32_t ah_b = sb + SM_A + (uint32_t)buf * 16384u;
        const uint32_t bh_b = sb + SM_B + (uint32_t)buf * 12288u;

#pragma unroll
        for (int kp = 0; kp < 2; ++kp) {
            uint32_t bh[3][4];
#pragma unroll
            for (int nt = 0; nt < 3; ++nt) {
                uint32_t boff = sw128((uint32_t)((b_row + nt * 8) * 128 + kp * 64 + b_koff));
                ldsm_x4(bh[nt], bh_b + boff);
            }
#pragma unroll
            for (int ks2 = 0; ks2 < 2; ++ks2) {
                const int ks = kp * 2 + ks2;
                uint32_t a[4][4];
#pragma unroll
                for (int mt = 0; mt < 4; ++mt) {
                    uint32_t aoff = sw128((uint32_t)((a_row8 + mt * 16) * 128 + ks * 32 + a_koff));
                    ldsm_x4(a[mt], ah_b + aoff);
                }
#pragma unroll
                for (int mt = 0; mt < 4; ++mt)
#pragma unroll
                    for (int nt = 0; nt < 3; ++nt)
                        mma16816(acc[mt][nt], a[mt], bh[nt][2 * ks2], bh[nt][2 * ks2 + 1]);
            }
        }

        // wait for stage it+1's W (committed a full iteration ago)
        if (it + 2 < NITER) cp_wait1();
        else                cp_wait0();
        __syncthreads();
    }

    // ---------------- epilogue ----------------
    const int r0 = m0 + wm * 64 + (lid >> 2);
    const int c0 = wn * 24 + (lid & 3) * 2;
#pragma unroll
    for (int nt = 0; nt < 3; ++nt) {
        const int col = c0 + nt * 8;
        const float b0 = bias[col], b1 = bias[col + 1];
#pragma unroll
        for (int mt = 0; mt < 4; ++mt) {
            const int row = r0 + mt * 16;
            float2 v0 = make_float2(acc[mt][nt][0] + b0, acc[mt][nt][1] + b1);
            float2 v1 = make_float2(acc[mt][nt][2] + b0, acc[mt][nt][3] + b1);
            *reinterpret_cast<float2*>(out + (size_t)row * NH + col) = v0;
            *reinterpret_cast<float2*>(out + (size_t)(row + 8) * NH + col) = v1;
        }
    }
}

extern "C" void kernel_launch(void* const* d_in, const int* in_sizes, int n_in,
                              void* d_out, int out_size) {
    const float* x    = (const float*)d_in[0];  // [16384, 2048]
    const float* W    = (const float*)d_in[1];  // [96, 2048]
    const float* bias = (const float*)d_in[2];  // [96]
    float* out        = (float*)d_out;          // [16384, 96]

    cudaFuncSetAttribute(mh96_kernel, cudaFuncAttributeMaxDynamicSharedMemorySize, SM_TOTAL);
    convW_kernel<<<(NH * KT) / 256, 256>>>(W);
    mh96_kernel<<<16384 / M_TILE, NTHREADS, SM_TOTAL>>>(x, bias, out);
}